// round 2
// baseline (speedup 1.0000x reference)
#include <cuda_runtime.h>
#include <math.h>

#define B 64
#define N 4096
#define D 256
#define S 8
#define NCHUNK 16

// Scratch (device globals; no allocation)
__device__ float g_xln[(size_t)B * N * D];        // 256 MB
__device__ float g_slots[B * S * D];
__device__ float g_qt[B * S * D];                 // scale-folded q @ Wk
__device__ float g_attn[(size_t)B * S * N];       // logits -> attn, 8 MB
__device__ float g_ut[B * S * D];                 // attn @ xln
__device__ float g_utp[(size_t)NCHUNK * B * S * D];

__device__ __forceinline__ float warp_sum(float v) {
    #pragma unroll
    for (int o = 16; o > 0; o >>= 1) v += __shfl_xor_sync(0xffffffffu, v, o);
    return v;
}

// LayerNorm one row of 256 floats, one warp. src/dst 16B aligned.
__device__ __forceinline__ void ln_row_warp(const float* __restrict__ src,
                                            float* __restrict__ dst,
                                            const float* __restrict__ g,
                                            const float* __restrict__ be,
                                            int lane) {
    float4 a = ((const float4*)src)[lane];
    float4 c = ((const float4*)src)[lane + 32];
    float s = a.x + a.y + a.z + a.w + c.x + c.y + c.z + c.w;
    float q = a.x * a.x + a.y * a.y + a.z * a.z + a.w * a.w
            + c.x * c.x + c.y * c.y + c.z * c.z + c.w * c.w;
    s = warp_sum(s);
    q = warp_sum(q);
    float mu = s * (1.0f / 256.0f);
    float var = q * (1.0f / 256.0f) - mu * mu;
    float rs = rsqrtf(var + 1e-5f);
    float4 g0 = ((const float4*)g)[lane], g1 = ((const float4*)g)[lane + 32];
    float4 e0 = ((const float4*)be)[lane], e1 = ((const float4*)be)[lane + 32];
    float4 o0, o1;
    o0.x = (a.x - mu) * rs * g0.x + e0.x;
    o0.y = (a.y - mu) * rs * g0.y + e0.y;
    o0.z = (a.z - mu) * rs * g0.z + e0.z;
    o0.w = (a.w - mu) * rs * g0.w + e0.w;
    o1.x = (c.x - mu) * rs * g1.x + e1.x;
    o1.y = (c.y - mu) * rs * g1.y + e1.y;
    o1.z = (c.z - mu) * rs * g1.z + e1.z;
    o1.w = (c.w - mu) * rs * g1.w + e1.w;
    ((float4*)dst)[lane] = o0;
    ((float4*)dst)[lane + 32] = o1;
}

// ---------------- Kernel 0: xln = LN(x) ----------------
__global__ __launch_bounds__(256) void ln_x_kernel(const float* __restrict__ x,
                                                   const float* __restrict__ g,
                                                   const float* __restrict__ be) {
    int row = blockIdx.x * 8 + (threadIdx.x >> 5);
    int lane = threadIdx.x & 31;
    ln_row_warp(x + (size_t)row * D, g_xln + (size_t)row * D, g, be, lane);
}

// ---------------- Kernel 1: slots init ----------------
__global__ __launch_bounds__(256) void init_slots_kernel(const float* __restrict__ noise,
                                                         const float* __restrict__ mu,
                                                         const float* __restrict__ ls) {
    int i = blockIdx.x * 256 + threadIdx.x;
    int d = i & (D - 1);
    g_slots[i] = mu[d] + noise[i] * expf(ls[d]);
}

// ---------------- Kernel 2: q~ = scale * (LN(slots) @ Wq^T) @ Wk ----------------
__global__ __launch_bounds__(256) void qproj_kernel(const float* __restrict__ Wq,
                                                    const float* __restrict__ Wk,
                                                    const float* __restrict__ gg,
                                                    const float* __restrict__ bb) {
    __shared__ __align__(16) float sln[S * D];
    __shared__ float qb[S * D];
    int b = blockIdx.x, tid = threadIdx.x;
    int w = tid >> 5, lane = tid & 31;
    ln_row_warp(g_slots + b * S * D + w * D, sln + w * D, gg, bb, lane);
    __syncthreads();
    // q[s][e], thread e = tid
    float acc[S];
    #pragma unroll
    for (int s = 0; s < S; s++) acc[s] = 0.f;
    const float4* wq = (const float4*)(Wq + (size_t)tid * D);
    for (int i = 0; i < D / 4; i++) {
        float4 wv = wq[i];
        #pragma unroll
        for (int s = 0; s < S; s++) {
            const float* p = &sln[s * D + i * 4];
            acc[s] += p[0] * wv.x + p[1] * wv.y + p[2] * wv.z + p[3] * wv.w;
        }
    }
    #pragma unroll
    for (int s = 0; s < S; s++) qb[s * D + tid] = acc[s];
    __syncthreads();
    // q~[s][d] = sum_e q[s][e] * Wk[e][d], thread d = tid (coalesced Wk reads)
    float a2[S];
    #pragma unroll
    for (int s = 0; s < S; s++) a2[s] = 0.f;
    for (int e = 0; e < D; e++) {
        float wv = Wk[(size_t)e * D + tid];
        #pragma unroll
        for (int s = 0; s < S; s++) a2[s] += qb[s * D + e] * wv;
    }
    const float sc = 0.0625f;  // 256^-0.5
    #pragma unroll
    for (int s = 0; s < S; s++) g_qt[b * S * D + s * D + tid] = a2[s] * sc;
}

// ---------------- Kernel 3: logits = q~ @ xln^T ----------------
__global__ __launch_bounds__(256) void logits_kernel() {
    __shared__ float qs[S * D];
    __shared__ float xs[16 * 513];
    int b = blockIdx.y, tid = threadIdx.x;
    int n0 = blockIdx.x * 512;
    for (int i = tid; i < S * D; i += 256) qs[i] = g_qt[b * S * D + i];
    float acc0[S], acc1[S];
    #pragma unroll
    for (int s = 0; s < S; s++) { acc0[s] = 0.f; acc1[s] = 0.f; }
    const float* xb = g_xln + ((size_t)b * N + n0) * D;
    for (int d0 = 0; d0 < D; d0 += 16) {
        __syncthreads();
        #pragma unroll 4
        for (int p = 0; p < 32; p++) {
            int idx = p * 256 + tid;
            int r = idx >> 4, c = idx & 15;
            xs[c * 513 + r] = xb[(size_t)r * D + d0 + c];
        }
        __syncthreads();
        #pragma unroll
        for (int dd = 0; dd < 16; dd++) {
            float a0 = xs[dd * 513 + tid];
            float a1 = xs[dd * 513 + 256 + tid];
            #pragma unroll
            for (int s = 0; s < S; s++) {
                float qv = qs[s * D + d0 + dd];
                acc0[s] += a0 * qv;
                acc1[s] += a1 * qv;
            }
        }
    }
    #pragma unroll
    for (int s = 0; s < S; s++) {
        float* lr = g_attn + (size_t)(b * S + s) * N + n0;
        lr[tid] = acc0[s];
        lr[256 + tid] = acc1[s];
    }
}

// ---------------- Kernel 4: softmax + eps renorm (in place) ----------------
__global__ __launch_bounds__(256) void softmax_kernel() {
    __shared__ __align__(16) float buf[N];
    __shared__ float red[8];
    int row = blockIdx.x, tid = threadIdx.x;
    int lane = tid & 31, w = tid >> 5;
    float* lr = g_attn + (size_t)row * N;
    float m = -3.4e38f;
    for (int i = tid; i < N / 4; i += 256) {
        float4 v = ((const float4*)lr)[i];
        ((float4*)buf)[i] = v;
        m = fmaxf(m, fmaxf(fmaxf(v.x, v.y), fmaxf(v.z, v.w)));
    }
    #pragma unroll
    for (int o = 16; o > 0; o >>= 1) m = fmaxf(m, __shfl_xor_sync(0xffffffffu, m, o));
    if (lane == 0) red[w] = m;
    __syncthreads();
    m = red[0];
    #pragma unroll
    for (int i = 1; i < 8; i++) m = fmaxf(m, red[i]);
    float sum = 0.f;
    for (int i = tid; i < N; i += 256) {
        float e = expf(buf[i] - m);
        buf[i] = e;
        sum += e;
    }
    sum = warp_sum(sum);
    __syncthreads();
    if (lane == 0) red[w] = sum;
    __syncthreads();
    sum = 0.f;
    #pragma unroll
    for (int i = 0; i < 8; i++) sum += red[i];
    float inv = 1.f / sum;
    const float rn = 1.f / (1.f + (float)N * 1e-8f);
    for (int i = tid; i < N; i += 256) lr[i] = (buf[i] * inv + 1e-8f) * rn;
}

// ---------------- Kernel 5: u~ partials = attn @ xln (split-K) ----------------
__global__ __launch_bounds__(128) void ut_kernel() {
    __shared__ float at[S * 256];
    int b = blockIdx.y, ch = blockIdx.x, tid = threadIdx.x;
    int n0 = ch * 256;
    for (int i = tid; i < S * 256; i += 128) {
        int s = i >> 8, n = i & 255;
        at[i] = g_attn[(size_t)(b * S + s) * N + n0 + n];
    }
    __syncthreads();
    float2 acc[S];
    #pragma unroll
    for (int s = 0; s < S; s++) { acc[s].x = 0.f; acc[s].y = 0.f; }
    const float2* xb = ((const float2*)g_xln) + ((size_t)(b * N + n0)) * (D / 2) + tid;
    for (int n = 0; n < 256; n++) {
        float2 xv = xb[(size_t)n * (D / 2)];
        #pragma unroll
        for (int s = 0; s < S; s++) {
            float a = at[s * 256 + n];
            acc[s].x += a * xv.x;
            acc[s].y += a * xv.y;
        }
    }
    float* up = g_utp + (size_t)(ch * B + b) * S * D;
    #pragma unroll
    for (int s = 0; s < S; s++) ((float2*)(up + s * D))[tid] = acc[s];
}

__global__ __launch_bounds__(256) void ut_reduce_kernel() {
    int i = blockIdx.x * 256 + threadIdx.x;  // over B*S*D
    float s = 0.f;
    #pragma unroll
    for (int c = 0; c < NCHUNK; c++) s += g_utp[(size_t)c * B * S * D + i];
    g_ut[i] = s;
}

// ---------------- Kernel 6: updates = u~ @ Wv^T, then GRU ----------------
__global__ __launch_bounds__(256) void gru_kernel(const float* __restrict__ Wv,
                                                  const float* __restrict__ Wih,
                                                  const float* __restrict__ Whh,
                                                  const float* __restrict__ bih,
                                                  const float* __restrict__ bhh) {
    __shared__ float uts[S * D];
    __shared__ float upd[S * D];
    __shared__ float prev[S * D];
    int b = blockIdx.x, tid = threadIdx.x;
    for (int i = tid; i < S * D; i += 256) {
        uts[i] = g_ut[b * S * D + i];
        prev[i] = g_slots[b * S * D + i];
    }
    __syncthreads();
    // updates[s][e], thread e = tid
    float acc[S];
    #pragma unroll
    for (int s = 0; s < S; s++) acc[s] = 0.f;
    const float4* wv4 = (const float4*)(Wv + (size_t)tid * D);
    for (int i = 0; i < D / 4; i++) {
        float4 wv = wv4[i];
        #pragma unroll
        for (int s = 0; s < S; s++) {
            const float* p = &uts[s * D + i * 4];
            acc[s] += p[0] * wv.x + p[1] * wv.y + p[2] * wv.z + p[3] * wv.w;
        }
    }
    #pragma unroll
    for (int s = 0; s < S; s++) upd[s * D + tid] = acc[s];
    __syncthreads();
    // gates, thread d = tid
    float gi[3][S], gh[3][S];
    for (int gsel = 0; gsel < 3; gsel++) {
        int r = gsel * D + tid;
        const float4* wi = (const float4*)(Wih + (size_t)r * D);
        const float4* wh = (const float4*)(Whh + (size_t)r * D);
        float ai[S], ah[S];
        #pragma unroll
        for (int s = 0; s < S; s++) { ai[s] = 0.f; ah[s] = 0.f; }
        for (int i = 0; i < D / 4; i++) {
            float4 a = wi[i], c = wh[i];
            #pragma unroll
            for (int s = 0; s < S; s++) {
                const float* pu = &upd[s * D + i * 4];
                const float* pp = &prev[s * D + i * 4];
                ai[s] += pu[0] * a.x + pu[1] * a.y + pu[2] * a.z + pu[3] * a.w;
                ah[s] += pp[0] * c.x + pp[1] * c.y + pp[2] * c.z + pp[3] * c.w;
            }
        }
        float bi_ = bih[r], bh_ = bhh[r];
        #pragma unroll
        for (int s = 0; s < S; s++) {
            gi[gsel][s] = ai[s] + bi_;
            gh[gsel][s] = ah[s] + bh_;
        }
    }
    #pragma unroll
    for (int s = 0; s < S; s++) {
        float r = 1.f / (1.f + expf(-(gi[0][s] + gh[0][s])));
        float z = 1.f / (1.f + expf(-(gi[1][s] + gh[1][s])));
        float nn = tanhf(gi[2][s] + r * gh[2][s]);
        float hv = prev[s * D + tid];
        g_slots[b * S * D + s * D + tid] = (1.f - z) * nn + z * hv;
    }
}

// ---------------- Kernel 7: MLP + residual ----------------
__global__ __launch_bounds__(256) void mlp_kernel(const float* __restrict__ W1,
                                                  const float* __restrict__ b1,
                                                  const float* __restrict__ W2,
                                                  const float* __restrict__ b2,
                                                  const float* __restrict__ gg,
                                                  const float* __restrict__ bb,
                                                  float* __restrict__ out, int write_out) {
    __shared__ __align__(16) float sln[S * D];
    __shared__ float hb[S * D];
    int b = blockIdx.x, tid = threadIdx.x;
    int w = tid >> 5, lane = tid & 31;
    ln_row_warp(g_slots + b * S * D + w * D, sln + w * D, gg, bb, lane);
    __syncthreads();
    float acc[S];
    #pragma unroll
    for (int s = 0; s < S; s++) acc[s] = 0.f;
    const float4* w1 = (const float4*)(W1 + (size_t)tid * D);
    for (int i = 0; i < D / 4; i++) {
        float4 wv = w1[i];
        #pragma unroll
        for (int s = 0; s < S; s++) {
            const float* p = &sln[s * D + i * 4];
            acc[s] += p[0] * wv.x + p[1] * wv.y + p[2] * wv.z + p[3] * wv.w;
        }
    }
    float bv = b1[tid];
    #pragma unroll
    for (int s = 0; s < S; s++) hb[s * D + tid] = fmaxf(acc[s] + bv, 0.f);
    __syncthreads();
    float a2[S];
    #pragma unroll
    for (int s = 0; s < S; s++) a2[s] = 0.f;
    const float4* w2 = (const float4*)(W2 + (size_t)tid * D);
    for (int i = 0; i < D / 4; i++) {
        float4 wv = w2[i];
        #pragma unroll
        for (int s = 0; s < S; s++) {
            const float* p = &hb[s * D + i * 4];
            a2[s] += p[0] * wv.x + p[1] * wv.y + p[2] * wv.z + p[3] * wv.w;
        }
    }
    float b2v = b2[tid];
    if (write_out) {
        #pragma unroll
        for (int s = 0; s < S; s++)
            out[b * S * D + s * D + tid] = g_slots[b * S * D + s * D + tid] + a2[s] + b2v;
    } else {
        #pragma unroll
        for (int s = 0; s < S; s++)
            g_slots[b * S * D + s * D + tid] = g_slots[b * S * D + s * D + tid] + a2[s] + b2v;
    }
}

extern "C" void kernel_launch(void* const* d_in, const int* in_sizes, int n_in,
                              void* d_out, int out_size) {
    const float* x        = (const float*)d_in[0];
    const float* noise    = (const float*)d_in[1];
    const float* slots_mu = (const float*)d_in[2];
    const float* slots_ls = (const float*)d_in[3];
    const float* Wq       = (const float*)d_in[4];
    const float* Wk       = (const float*)d_in[5];
    const float* Wv       = (const float*)d_in[6];
    const float* W_ih     = (const float*)d_in[7];
    const float* W_hh     = (const float*)d_in[8];
    const float* b_ih     = (const float*)d_in[9];
    const float* b_hh     = (const float*)d_in[10];
    const float* W1       = (const float*)d_in[11];
    const float* b1       = (const float*)d_in[12];
    const float* W2       = (const float*)d_in[13];
    const float* b2       = (const float*)d_in[14];
    const float* g_in     = (const float*)d_in[15];
    const float* be_in    = (const float*)d_in[16];
    const float* g_sl     = (const float*)d_in[17];
    const float* be_sl    = (const float*)d_in[18];
    const float* g_ff     = (const float*)d_in[19];
    const float* be_ff    = (const float*)d_in[20];
    float* out = (float*)d_out;

    ln_x_kernel<<<(B * N) / 8, 256>>>(x, g_in, be_in);
    init_slots_kernel<<<(B * S * D) / 256, 256>>>(noise, slots_mu, slots_ls);
    for (int it = 0; it < 3; it++) {
        qproj_kernel<<<B, 256>>>(Wq, Wk, g_sl, be_sl);
        logits_kernel<<<dim3(N / 512, B), 256>>>();
        softmax_kernel<<<B * S, 256>>>();
        ut_kernel<<<dim3(NCHUNK, B), 128>>>();
        ut_reduce_kernel<<<(B * S * D) / 256, 256>>>();
        gru_kernel<<<B, 256>>>(Wv, W_ih, W_hh, b_ih, b_hh);
        mlp_kernel<<<B, 256>>>(W1, b1, W2, b2, g_ff, be_ff, out, it == 2 ? 1 : 0);
    }
}

// round 3
// speedup vs baseline: 1.0800x; 1.0800x over previous
#include <cuda_runtime.h>
#include <math.h>

#define B 64
#define N 4096
#define D 256
#define S 8
#define NCHUNK 16
#define CH 256     // rows per chunk
#define TILE 16    // rows per tile
#define NT 16      // tiles per chunk
#define XPAD 260   // padded smem row stride (floats)

// Scratch (device globals; no allocation)
__device__ float g_xln[(size_t)B * N * D];                 // 256 MB
__device__ float g_slots[B * S * D];
__device__ float g_qt[B * S * D];                          // scale-folded q @ Wk
__device__ float g_ut[B * S * D];                          // final updates (x-space)
__device__ float g_Up[(size_t)NCHUNK * B * S * D];         // chunk partial weighted sums
__device__ float g_xsp[(size_t)NCHUNK * B * D];            // chunk partial plain sums
__device__ float g_m[NCHUNK * B * S];
__device__ float g_z[NCHUNK * B * S];

__device__ __forceinline__ float warp_sum(float v) {
    #pragma unroll
    for (int o = 16; o > 0; o >>= 1) v += __shfl_xor_sync(0xffffffffu, v, o);
    return v;
}

// LayerNorm one row of 256 floats, one warp. src/dst 16B aligned.
__device__ __forceinline__ void ln_row_warp(const float* __restrict__ src,
                                            float* __restrict__ dst,
                                            const float* __restrict__ g,
                                            const float* __restrict__ be,
                                            int lane) {
    float4 a = ((const float4*)src)[lane];
    float4 c = ((const float4*)src)[lane + 32];
    float s = a.x + a.y + a.z + a.w + c.x + c.y + c.z + c.w;
    float q = a.x * a.x + a.y * a.y + a.z * a.z + a.w * a.w
            + c.x * c.x + c.y * c.y + c.z * c.z + c.w * c.w;
    s = warp_sum(s);
    q = warp_sum(q);
    float mu = s * (1.0f / 256.0f);
    float var = q * (1.0f / 256.0f) - mu * mu;
    float rs = rsqrtf(var + 1e-5f);
    float4 g0 = ((const float4*)g)[lane], g1 = ((const float4*)g)[lane + 32];
    float4 e0 = ((const float4*)be)[lane], e1 = ((const float4*)be)[lane + 32];
    float4 o0, o1;
    o0.x = (a.x - mu) * rs * g0.x + e0.x;
    o0.y = (a.y - mu) * rs * g0.y + e0.y;
    o0.z = (a.z - mu) * rs * g0.z + e0.z;
    o0.w = (a.w - mu) * rs * g0.w + e0.w;
    o1.x = (c.x - mu) * rs * g1.x + e1.x;
    o1.y = (c.y - mu) * rs * g1.y + e1.y;
    o1.z = (c.z - mu) * rs * g1.z + e1.z;
    o1.w = (c.w - mu) * rs * g1.w + e1.w;
    ((float4*)dst)[lane] = o0;
    ((float4*)dst)[lane + 32] = o1;
}

// ---------------- Kernel 0: xln = LN(x) ----------------
__global__ __launch_bounds__(256) void ln_x_kernel(const float* __restrict__ x,
                                                   const float* __restrict__ g,
                                                   const float* __restrict__ be) {
    int row = blockIdx.x * 8 + (threadIdx.x >> 5);
    int lane = threadIdx.x & 31;
    ln_row_warp(x + (size_t)row * D, g_xln + (size_t)row * D, g, be, lane);
}

// ---------------- Kernel 1: slots init ----------------
__global__ __launch_bounds__(256) void init_slots_kernel(const float* __restrict__ noise,
                                                         const float* __restrict__ mu,
                                                         const float* __restrict__ ls) {
    int i = blockIdx.x * 256 + threadIdx.x;
    int d = i & (D - 1);
    g_slots[i] = mu[d] + noise[i] * expf(ls[d]);
}

// ---------------- Kernel 2: q~ = scale * (LN(slots) @ Wq^T) @ Wk ----------------
// 4 slots per block, grid = B*2
__global__ __launch_bounds__(256) void qproj_kernel(const float* __restrict__ Wq,
                                                    const float* __restrict__ Wk,
                                                    const float* __restrict__ gg,
                                                    const float* __restrict__ bb) {
    __shared__ __align__(16) float sln[4 * D];
    __shared__ float qb[4 * D];
    int bid = blockIdx.x;
    int b = bid >> 1, sg = bid & 1;
    int tid = threadIdx.x, w = tid >> 5, lane = tid & 31;
    if (w < 4)
        ln_row_warp(g_slots + b * S * D + (sg * 4 + w) * D, sln + w * D, gg, bb, lane);
    __syncthreads();
    float acc[4] = {0.f, 0.f, 0.f, 0.f};
    const float4* wq = (const float4*)(Wq + (size_t)tid * D);
    for (int i = 0; i < D / 4; i++) {
        float4 wv = wq[i];
        #pragma unroll
        for (int s = 0; s < 4; s++) {
            const float* p = &sln[s * D + i * 4];
            acc[s] += p[0] * wv.x + p[1] * wv.y + p[2] * wv.z + p[3] * wv.w;
        }
    }
    #pragma unroll
    for (int s = 0; s < 4; s++) qb[s * D + tid] = acc[s];
    __syncthreads();
    float a2[4] = {0.f, 0.f, 0.f, 0.f};
    for (int e = 0; e < D; e++) {
        float wv = Wk[(size_t)e * D + tid];
        #pragma unroll
        for (int s = 0; s < 4; s++) a2[s] += qb[s * D + e] * wv;
    }
    const float sc = 0.0625f;  // 256^-0.5
    #pragma unroll
    for (int s = 0; s < 4; s++)
        g_qt[b * S * D + (sg * 4 + s) * D + tid] = a2[s] * sc;
}

// ---------------- Kernel 3: fused flash attention over a chunk ----------------
// grid (NCHUNK, B), 256 threads. Produces per-chunk (m, Z, U, xsum) partials.
__global__ __launch_bounds__(256) void fused_attn_kernel() {
    __shared__ __align__(16) float qs[S * XPAD];
    __shared__ __align__(16) float xs[TILE * XPAD];
    __shared__ float lw2[2][TILE * S];
    __shared__ float ws[TILE * S];
    __shared__ float s_alpha[S], s_mnew[S];
    int b = blockIdx.y, ch = blockIdx.x, tid = threadIdx.x;

    for (int i = tid; i < S * D; i += 256)
        qs[(i >> 8) * XPAD + (i & 255)] = g_qt[b * S * D + i];

    const float* xb = g_xln + ((size_t)b * N + (size_t)ch * CH) * D;
    float U[S];
    #pragma unroll
    for (int s = 0; s < S; s++) U[s] = 0.f;
    float xacc = 0.f;
    float m_run = -3.4e38f, z_run = 0.f;  // live only in threads tid<8

    const int l_half = tid >> 7, l_r = (tid >> 3) & 15, l_s = tid & 7;

    // prefetch tile 0
    float4 pf[4];
    #pragma unroll
    for (int p = 0; p < 4; p++) pf[p] = ((const float4*)xb)[p * 256 + tid];

    for (int t = 0; t < NT; t++) {
        __syncthreads();  // previous tile fully consumed
        #pragma unroll
        for (int p = 0; p < 4; p++) {
            int idx = p * 256 + tid;
            int r = idx >> 6, c = idx & 63;
            *(float4*)&xs[r * XPAD + c * 4] = pf[p];
        }
        __syncthreads();
        if (t + 1 < NT) {
            const float* xbn = xb + (size_t)(t + 1) * TILE * D;
            #pragma unroll
            for (int p = 0; p < 4; p++) pf[p] = ((const float4*)xbn)[p * 256 + tid];
        }
        // logits: (half, r, s) threads, each a 128-length partial dot
        {
            const float4* xr = (const float4*)&xs[l_r * XPAD + l_half * 128];
            const float4* qr = (const float4*)&qs[l_s * XPAD + l_half * 128];
            float a = 0.f;
            #pragma unroll
            for (int k = 0; k < 32; k++) {
                float4 xv = xr[k], qv = qr[k];
                a += xv.x * qv.x + xv.y * qv.y + xv.z * qv.z + xv.w * qv.w;
            }
            lw2[l_half][l_r * S + l_s] = a;
        }
        __syncthreads();
        if (tid < 8) {
            int s = tid;
            float tm = -3.4e38f;
            #pragma unroll
            for (int r = 0; r < TILE; r++)
                tm = fmaxf(tm, lw2[0][r * S + s] + lw2[1][r * S + s]);
            float mn = fmaxf(m_run, tm);
            s_alpha[s] = __expf(m_run - mn);
            s_mnew[s] = mn;
            m_run = mn;
        }
        __syncthreads();
        if (tid < 128) {
            int r = tid >> 3, s = tid & 7;
            ws[tid] = __expf(lw2[0][r * S + s] + lw2[1][r * S + s] - s_mnew[s]);
        }
        __syncthreads();
        if (tid < 8) {
            int s = tid;
            float zs = 0.f;
            #pragma unroll
            for (int r = 0; r < TILE; r++) zs += ws[r * S + s];
            z_run = z_run * s_alpha[s] + zs;
        }
        // accumulate: thread owns column d = tid
        #pragma unroll
        for (int s = 0; s < S; s++) U[s] *= s_alpha[s];
        #pragma unroll
        for (int r = 0; r < TILE; r++) {
            float xv = xs[r * XPAD + tid];
            xacc += xv;
            #pragma unroll
            for (int s = 0; s < S; s++) U[s] += ws[r * S + s] * xv;
        }
    }
    size_t base = (size_t)ch * B + b;
    #pragma unroll
    for (int s = 0; s < S; s++) g_Up[base * S * D + s * D + tid] = U[s];
    g_xsp[base * D + tid] = xacc;
    if (tid < 8) {
        g_m[base * S + tid] = m_run;
        g_z[base * S + tid] = z_run;
    }
}

// ---------------- Kernel 4: combine chunk partials -> updates (x-space) ----------------
__global__ __launch_bounds__(256) void attn_reduce_kernel() {
    __shared__ float ef[S][NCHUNK];
    __shared__ float zinv[S];
    int b = blockIdx.x, tid = threadIdx.x;
    if (tid < 8) {
        int s = tid;
        float mg = -3.4e38f;
        #pragma unroll
        for (int c = 0; c < NCHUNK; c++)
            mg = fmaxf(mg, g_m[(c * B + b) * S + s]);
        float zg = 0.f;
        #pragma unroll
        for (int c = 0; c < NCHUNK; c++) {
            float e = __expf(g_m[(c * B + b) * S + s] - mg);
            ef[s][c] = e;
            zg += g_z[(c * B + b) * S + s] * e;
        }
        zinv[s] = 1.f / zg;
    }
    __syncthreads();
    float xsum = 0.f;
    #pragma unroll
    for (int c = 0; c < NCHUNK; c++)
        xsum += g_xsp[((size_t)c * B + b) * D + tid];
    const float rn = 1.f / (1.f + (float)N * 1e-8f);
    #pragma unroll
    for (int s = 0; s < S; s++) {
        float u = 0.f;
        #pragma unroll
        for (int c = 0; c < NCHUNK; c++)
            u += g_Up[(((size_t)c * B + b) * S + s) * D + tid] * ef[s][c];
        g_ut[b * S * D + s * D + tid] = (u * zinv[s] + 1e-8f * xsum) * rn;
    }
}

// ---------------- Kernel 5: updates = u~ @ Wv^T, then GRU (4 slots/block) ----------------
__global__ __launch_bounds__(256) void gru_kernel(const float* __restrict__ Wv,
                                                  const float* __restrict__ Wih,
                                                  const float* __restrict__ Whh,
                                                  const float* __restrict__ bih,
                                                  const float* __restrict__ bhh) {
    __shared__ float uts[4 * D];
    __shared__ float upd[4 * D];
    __shared__ float prev[4 * D];
    int bid = blockIdx.x;
    int b = bid >> 1, sg = bid & 1;
    int tid = threadIdx.x;
    int so = b * S * D + sg * 4 * D;
    for (int i = tid; i < 4 * D; i += 256) {
        uts[i] = g_ut[so + i];
        prev[i] = g_slots[so + i];
    }
    __syncthreads();
    float acc[4] = {0.f, 0.f, 0.f, 0.f};
    const float4* wv4 = (const float4*)(Wv + (size_t)tid * D);
    for (int i = 0; i < D / 4; i++) {
        float4 wv = wv4[i];
        #pragma unroll
        for (int s = 0; s < 4; s++) {
            const float* p = &uts[s * D + i * 4];
            acc[s] += p[0] * wv.x + p[1] * wv.y + p[2] * wv.z + p[3] * wv.w;
        }
    }
    #pragma unroll
    for (int s = 0; s < 4; s++) upd[s * D + tid] = acc[s];
    __syncthreads();
    float gi[3][4], gh[3][4];
    for (int gsel = 0; gsel < 3; gsel++) {
        int r = gsel * D + tid;
        const float4* wi = (const float4*)(Wih + (size_t)r * D);
        const float4* wh = (const float4*)(Whh + (size_t)r * D);
        float ai[4] = {0.f, 0.f, 0.f, 0.f}, ah[4] = {0.f, 0.f, 0.f, 0.f};
        for (int i = 0; i < D / 4; i++) {
            float4 a = wi[i], c = wh[i];
            #pragma unroll
            for (int s = 0; s < 4; s++) {
                const float* pu = &upd[s * D + i * 4];
                const float* pp = &prev[s * D + i * 4];
                ai[s] += pu[0] * a.x + pu[1] * a.y + pu[2] * a.z + pu[3] * a.w;
                ah[s] += pp[0] * c.x + pp[1] * c.y + pp[2] * c.z + pp[3] * c.w;
            }
        }
        float bi_ = bih[r], bh_ = bhh[r];
        #pragma unroll
        for (int s = 0; s < 4; s++) {
            gi[gsel][s] = ai[s] + bi_;
            gh[gsel][s] = ah[s] + bh_;
        }
    }
    #pragma unroll
    for (int s = 0; s < 4; s++) {
        float r = 1.f / (1.f + expf(-(gi[0][s] + gh[0][s])));
        float z = 1.f / (1.f + expf(-(gi[1][s] + gh[1][s])));
        float nn = tanhf(gi[2][s] + r * gh[2][s]);
        float hv = prev[s * D + tid];
        g_slots[so + s * D + tid] = (1.f - z) * nn + z * hv;
    }
}

// ---------------- Kernel 6: MLP + residual (4 slots/block) ----------------
__global__ __launch_bounds__(256) void mlp_kernel(const float* __restrict__ W1,
                                                  const float* __restrict__ b1,
                                                  const float* __restrict__ W2,
                                                  const float* __restrict__ b2,
                                                  const float* __restrict__ gg,
                                                  const float* __restrict__ bb,
                                                  float* __restrict__ out, int write_out) {
    __shared__ __align__(16) float sln[4 * D];
    __shared__ float hb[4 * D];
    int bid = blockIdx.x;
    int b = bid >> 1, sg = bid & 1;
    int tid = threadIdx.x, w = tid >> 5, lane = tid & 31;
    int so = b * S * D + sg * 4 * D;
    if (w < 4)
        ln_row_warp(g_slots + so + w * D, sln + w * D, gg, bb, lane);
    __syncthreads();
    float acc[4] = {0.f, 0.f, 0.f, 0.f};
    const float4* w1 = (const float4*)(W1 + (size_t)tid * D);
    for (int i = 0; i < D / 4; i++) {
        float4 wv = w1[i];
        #pragma unroll
        for (int s = 0; s < 4; s++) {
            const float* p = &sln[s * D + i * 4];
            acc[s] += p[0] * wv.x + p[1] * wv.y + p[2] * wv.z + p[3] * wv.w;
        }
    }
    float bv = b1[tid];
    #pragma unroll
    for (int s = 0; s < 4; s++) hb[s * D + tid] = fmaxf(acc[s] + bv, 0.f);
    __syncthreads();
    float a2[4] = {0.f, 0.f, 0.f, 0.f};
    const float4* w2 = (const float4*)(W2 + (size_t)tid * D);
    for (int i = 0; i < D / 4; i++) {
        float4 wv = w2[i];
        #pragma unroll
        for (int s = 0; s < 4; s++) {
            const float* p = &hb[s * D + i * 4];
            a2[s] += p[0] * wv.x + p[1] * wv.y + p[2] * wv.z + p[3] * wv.w;
        }
    }
    float b2v = b2[tid];
    if (write_out) {
        #pragma unroll
        for (int s = 0; s < 4; s++)
            out[so + s * D + tid] = g_slots[so + s * D + tid] + a2[s] + b2v;
    } else {
        #pragma unroll
        for (int s = 0; s < 4; s++)
            g_slots[so + s * D + tid] = g_slots[so + s * D + tid] + a2[s] + b2v;
    }
}

extern "C" void kernel_launch(void* const* d_in, const int* in_sizes, int n_in,
                              void* d_out, int out_size) {
    const float* x        = (const float*)d_in[0];
    const float* noise    = (const float*)d_in[1];
    const float* slots_mu = (const float*)d_in[2];
    const float* slots_ls = (const float*)d_in[3];
    const float* Wq       = (const float*)d_in[4];
    const float* Wk       = (const float*)d_in[5];
    const float* Wv       = (const float*)d_in[6];
    const float* W_ih     = (const float*)d_in[7];
    const float* W_hh     = (const float*)d_in[8];
    const float* b_ih     = (const float*)d_in[9];
    const float* b_hh     = (const float*)d_in[10];
    const float* W1       = (const float*)d_in[11];
    const float* b1       = (const float*)d_in[12];
    const float* W2       = (const float*)d_in[13];
    const float* b2       = (const float*)d_in[14];
    const float* g_in     = (const float*)d_in[15];
    const float* be_in    = (const float*)d_in[16];
    const float* g_sl     = (const float*)d_in[17];
    const float* be_sl    = (const float*)d_in[18];
    const float* g_ff     = (const float*)d_in[19];
    const float* be_ff    = (const float*)d_in[20];
    float* out = (float*)d_out;

    ln_x_kernel<<<(B * N) / 8, 256>>>(x, g_in, be_in);
    init_slots_kernel<<<(B * S * D) / 256, 256>>>(noise, slots_mu, slots_ls);
    for (int it = 0; it < 3; it++) {
        qproj_kernel<<<B * 2, 256>>>(Wq, Wk, g_sl, be_sl);
        fused_attn_kernel<<<dim3(NCHUNK, B), 256>>>();
        attn_reduce_kernel<<<B, 256>>>();
        gru_kernel<<<B * 2, 256>>>(Wv, W_ih, W_hh, b_ih, b_hh);
        mlp_kernel<<<B * 2, 256>>>(W1, b1, W2, b2, g_ff, be_ff, out, it == 2 ? 1 : 0);
    }
}

// round 4
// speedup vs baseline: 1.1486x; 1.0635x over previous
#include <cuda_runtime.h>
#include <math.h>

#define B 64
#define N 4096
#define D 256
#define S 8
#define NP 16              // partials per batch (16 blocks over N)
#define RPW 64             // rows per warp
#define SC_LOG2E 0.09016844196f   // (1/16) * log2(e)

// ---- scratch (device globals) ----
__device__ float g_slots[B * S * D];
__device__ float g_qg[B * S * D];                 // (scale*log2e) * (q@Wk) * g_in
__device__ float g_cm[B * S];                     // -16*||qg||  (fixed -max, log2 domain)
__device__ float g_Up[(size_t)NP * B * S * D];    // 16 MB
__device__ float g_hs[(size_t)NP * B * D];
__device__ float g_z[NP * B * S];

__device__ __forceinline__ float warp_sum(float v) {
    #pragma unroll
    for (int o = 16; o > 0; o >>= 1) v += __shfl_xor_sync(0xffffffffu, v, o);
    return v;
}
__device__ __forceinline__ float ex2f(float v) {
    float r; asm("ex2.approx.f32 %0, %1;" : "=f"(r) : "f"(v)); return r;
}

// LayerNorm one row of 256 floats, one warp.
__device__ __forceinline__ void ln_row_warp(const float* __restrict__ src,
                                            float* __restrict__ dst,
                                            const float* __restrict__ g,
                                            const float* __restrict__ be,
                                            int lane) {
    float4 a = ((const float4*)src)[lane];
    float4 c = ((const float4*)src)[lane + 32];
    float s = a.x + a.y + a.z + a.w + c.x + c.y + c.z + c.w;
    float q = a.x * a.x + a.y * a.y + a.z * a.z + a.w * a.w
            + c.x * c.x + c.y * c.y + c.z * c.z + c.w * c.w;
    s = warp_sum(s);
    q = warp_sum(q);
    float mu = s * (1.0f / 256.0f);
    float var = q * (1.0f / 256.0f) - mu * mu;
    float rs = rsqrtf(var + 1e-5f);
    float4 g0 = ((const float4*)g)[lane], g1 = ((const float4*)g)[lane + 32];
    float4 e0 = ((const float4*)be)[lane], e1 = ((const float4*)be)[lane + 32];
    float4 o0, o1;
    o0.x = (a.x - mu) * rs * g0.x + e0.x;
    o0.y = (a.y - mu) * rs * g0.y + e0.y;
    o0.z = (a.z - mu) * rs * g0.z + e0.z;
    o0.w = (a.w - mu) * rs * g0.w + e0.w;
    o1.x = (c.x - mu) * rs * g1.x + e1.x;
    o1.y = (c.y - mu) * rs * g1.y + e1.y;
    o1.z = (c.z - mu) * rs * g1.z + e1.z;
    o1.w = (c.w - mu) * rs * g1.w + e1.w;
    ((float4*)dst)[lane] = o0;
    ((float4*)dst)[lane + 32] = o1;
}

// ---------------- slots init ----------------
__global__ __launch_bounds__(256) void init_slots_kernel(const float* __restrict__ noise,
                                                         const float* __restrict__ mu,
                                                         const float* __restrict__ ls) {
    int i = blockIdx.x * 256 + threadIdx.x;
    int d = i & (D - 1);
    g_slots[i] = mu[d] + noise[i] * expf(ls[d]);
}

// ---------------- qproj tail (shared by qproj0 and iter_kernel) ----------------
// fin: smem [4*D] final slots for this (b, half). Computes g_qg, g_cm for 4 slots.
__device__ __forceinline__ void qproj_tail(const float* fin, float* sln, float* qb,
                                           float* red, int b, int sb, int tid,
                                           const float* __restrict__ Wq,
                                           const float* __restrict__ Wk,
                                           const float* __restrict__ g_sl,
                                           const float* __restrict__ be_sl,
                                           const float* __restrict__ gin) {
    int w = tid >> 5, lane = tid & 31;
    if (w < 4) ln_row_warp(fin + w * D, sln + w * D, g_sl, be_sl, lane);
    __syncthreads();
    // q[s][e=tid] = LN(slot_s) . Wq[e][:]
    float acc[4] = {0.f, 0.f, 0.f, 0.f};
    const float4* wq = (const float4*)(Wq + (size_t)tid * D);
    for (int i = 0; i < D / 4; i++) {
        float4 wv = wq[i];
        #pragma unroll
        for (int s = 0; s < 4; s++) {
            const float* p = &sln[s * D + i * 4];
            acc[s] += p[0] * wv.x + p[1] * wv.y + p[2] * wv.z + p[3] * wv.w;
        }
    }
    #pragma unroll
    for (int s = 0; s < 4; s++) qb[s * D + tid] = acc[s];
    __syncthreads();
    // qt[s][d=tid] = sum_e q[s][e] * Wk[e][d]; fold scale*log2e and g_in
    float a2[4] = {0.f, 0.f, 0.f, 0.f};
    for (int e = 0; e < D; e++) {
        float wv = Wk[(size_t)e * D + tid];
        #pragma unroll
        for (int s = 0; s < 4; s++) a2[s] += qb[s * D + e] * wv;
    }
    float gv = gin[tid];
    float nrm[4];
    #pragma unroll
    for (int s = 0; s < 4; s++) {
        float qv = a2[s] * SC_LOG2E * gv;
        g_qg[(b * S + sb + s) * D + tid] = qv;
        nrm[s] = qv * qv;
    }
    #pragma unroll
    for (int s = 0; s < 4; s++) {
        float v = warp_sum(nrm[s]);
        if (lane == 0) red[s * 8 + w] = v;
    }
    __syncthreads();
    if (tid < 4) {
        float t = 0.f;
        #pragma unroll
        for (int i = 0; i < 8; i++) t += red[tid * 8 + i];
        g_cm[b * S + sb + tid] = -16.0f * sqrtf(t);
    }
}

__global__ __launch_bounds__(256) void qproj0_kernel(const float* __restrict__ Wq,
                                                     const float* __restrict__ Wk,
                                                     const float* __restrict__ g_sl,
                                                     const float* __restrict__ be_sl,
                                                     const float* __restrict__ gin) {
    __shared__ __align__(16) float fin[4 * D], sln[4 * D], qb[4 * D];
    __shared__ float red[32];
    int b = blockIdx.x >> 1, sb = (blockIdx.x & 1) * 4, tid = threadIdx.x;
    for (int i = tid; i < 4 * D; i += 256) fin[i] = g_slots[b * S * D + sb * D + i];
    __syncthreads();
    qproj_tail(fin, sln, qb, red, b, sb, tid, Wq, Wk, g_sl, be_sl, gin);
}

// ---------------- fused flash attention (warp-autonomous) ----------------
// grid (NP, B), 128 threads (4 warps). Warp handles 64 contiguous rows of raw x:
// on-the-fly LN -> logits vs register q -> fixed-max softmax -> rank-1 U update.
__global__ __launch_bounds__(128) void fused_attn_kernel(const float* __restrict__ x) {
    __shared__ __align__(16) float Usm[4 * S * D];   // 32 KB
    __shared__ __align__(16) float hssm[4 * D];
    __shared__ float zsm[4 * S];
    int b = blockIdx.y;
    int wid = threadIdx.x >> 5, lane = threadIdx.x & 31;
    int pidx = blockIdx.x * 4 + wid;   // 0..63 over N
    const float* xb = x + ((size_t)b * N + (size_t)pidx * RPW) * D + lane * 8;

    float qg[S][8];
    #pragma unroll
    for (int s = 0; s < S; s++) {
        float4 a = *(const float4*)&g_qg[(b * S + s) * D + lane * 8];
        float4 c = *(const float4*)&g_qg[(b * S + s) * D + lane * 8 + 4];
        qg[s][0] = a.x; qg[s][1] = a.y; qg[s][2] = a.z; qg[s][3] = a.w;
        qg[s][4] = c.x; qg[s][5] = c.y; qg[s][6] = c.z; qg[s][7] = c.w;
    }
    float cm[S];
    #pragma unroll
    for (int s = 0; s < S; s++) cm[s] = g_cm[b * S + s];

    float U[S][8];
    #pragma unroll
    for (int s = 0; s < S; s++)
        #pragma unroll
        for (int j = 0; j < 8; j++) U[s][j] = 0.f;
    float z[S];
    #pragma unroll
    for (int s = 0; s < S; s++) z[s] = 0.f;
    float hs[8];
    #pragma unroll
    for (int j = 0; j < 8; j++) hs[j] = 0.f;

    float4 pf0 = *(const float4*)xb;
    float4 pf1 = *(const float4*)(xb + 4);

    for (int r = 0; r < RPW; r++) {
        float xr[8] = {pf0.x, pf0.y, pf0.z, pf0.w, pf1.x, pf1.y, pf1.z, pf1.w};
        if (r + 1 < RPW) {
            const float* nx = xb + (size_t)(r + 1) * D;
            pf0 = *(const float4*)nx;
            pf1 = *(const float4*)(nx + 4);
        }
        float s1 = 0.f, s2 = 0.f;
        #pragma unroll
        for (int j = 0; j < 8; j++) { s1 += xr[j]; s2 = fmaf(xr[j], xr[j], s2); }
        #pragma unroll
        for (int o = 16; o > 0; o >>= 1) {
            s1 += __shfl_xor_sync(0xffffffffu, s1, o);
            s2 += __shfl_xor_sync(0xffffffffu, s2, o);
        }
        float mu = s1 * (1.0f / 256.0f);
        float var = fmaf(-mu, mu, s2 * (1.0f / 256.0f));
        float rs = rsqrtf(var + 1e-5f);
        float nb = -mu * rs;
        float h[8];
        #pragma unroll
        for (int j = 0; j < 8; j++) h[j] = fmaf(xr[j], rs, nb);
        float p[S];
        #pragma unroll
        for (int s = 0; s < S; s++) {
            float a = 0.f;
            #pragma unroll
            for (int j = 0; j < 8; j++) a = fmaf(qg[s][j], h[j], a);
            p[s] = a;
        }
        #pragma unroll
        for (int o = 16; o > 0; o >>= 1) {
            #pragma unroll
            for (int s = 0; s < S; s++)
                p[s] += __shfl_xor_sync(0xffffffffu, p[s], o);
        }
        #pragma unroll
        for (int s = 0; s < S; s++) {
            float w = ex2f(p[s] + cm[s]);   // arg <= 0 guaranteed (Cauchy-Schwarz)
            z[s] += w;
            #pragma unroll
            for (int j = 0; j < 8; j++) U[s][j] = fmaf(w, h[j], U[s][j]);
        }
        #pragma unroll
        for (int j = 0; j < 8; j++) hs[j] += h[j];
    }

    // block merge of 4 warps' partials
    #pragma unroll
    for (int s = 0; s < S; s++) {
        *(float4*)&Usm[(wid * S + s) * D + lane * 8] =
            make_float4(U[s][0], U[s][1], U[s][2], U[s][3]);
        *(float4*)&Usm[(wid * S + s) * D + lane * 8 + 4] =
            make_float4(U[s][4], U[s][5], U[s][6], U[s][7]);
    }
    *(float4*)&hssm[wid * D + lane * 8] = make_float4(hs[0], hs[1], hs[2], hs[3]);
    *(float4*)&hssm[wid * D + lane * 8 + 4] = make_float4(hs[4], hs[5], hs[6], hs[7]);
    if (lane == 0) {
        #pragma unroll
        for (int s = 0; s < S; s++) zsm[wid * S + s] = z[s];
    }
    __syncthreads();
    int tid = threadIdx.x;
    size_t pb = (size_t)blockIdx.x * B + b;
    #pragma unroll
    for (int k = 0; k < S; k++) {
        float a = 0.f;
        #pragma unroll
        for (int w = 0; w < 4; w++) a += Usm[(w * S + k) * D + tid] + Usm[(w * S + k) * D + tid + 128];
        // NOTE: above combines two d-positions incorrectly -- do separately:
        a = 0.f;
        #pragma unroll
        for (int w = 0; w < 4; w++) a += Usm[(w * S + k) * D + tid];
        float a2 = 0.f;
        #pragma unroll
        for (int w = 0; w < 4; w++) a2 += Usm[(w * S + k) * D + tid + 128];
        g_Up[(pb * S + k) * D + tid] = a;
        g_Up[(pb * S + k) * D + tid + 128] = a2;
    }
    {
        float a = 0.f, a2 = 0.f;
        #pragma unroll
        for (int w = 0; w < 4; w++) { a += hssm[w * D + tid]; a2 += hssm[w * D + tid + 128]; }
        g_hs[pb * D + tid] = a;
        g_hs[pb * D + tid + 128] = a2;
    }
    if (tid < S) {
        float a = 0.f;
        #pragma unroll
        for (int w = 0; w < 4; w++) a += zsm[w * S + tid];
        g_z[pb * S + tid] = a;
    }
}

// ---------------- fused epilogue: reduce + GRU + MLP + next qproj ----------------
__global__ __launch_bounds__(256) void iter_kernel(
    const float* __restrict__ gin, const float* __restrict__ bein,
    const float* __restrict__ Wv,
    const float* __restrict__ Wih, const float* __restrict__ Whh,
    const float* __restrict__ bih, const float* __restrict__ bhh,
    const float* __restrict__ W1, const float* __restrict__ b1,
    const float* __restrict__ W2, const float* __restrict__ b2,
    const float* __restrict__ g_ff, const float* __restrict__ be_ff,
    const float* __restrict__ g_sl, const float* __restrict__ be_sl,
    const float* __restrict__ Wq, const float* __restrict__ Wk,
    float* __restrict__ out, int last) {
    __shared__ __align__(16) float upd[4 * D], prev[4 * D], uv[4 * D];
    __shared__ __align__(16) float fin[4 * D], sln[4 * D], qb[4 * D];
    __shared__ float red[32];
    __shared__ float zin[4];
    int b = blockIdx.x >> 1, sb = (blockIdx.x & 1) * 4, tid = threadIdx.x;
    int w = tid >> 5, lane = tid & 31;

    // ---- reduce partials -> updates (x-space) ----
    float ua[4] = {0.f, 0.f, 0.f, 0.f};
    #pragma unroll
    for (int p = 0; p < NP; p++) {
        size_t base = ((size_t)p * B + b) * S * D + sb * D;
        #pragma unroll
        for (int s = 0; s < 4; s++) ua[s] += g_Up[base + s * D + tid];
    }
    float hsum = 0.f;
    #pragma unroll
    for (int p = 0; p < NP; p++) hsum += g_hs[((size_t)p * B + b) * D + tid];
    if (tid < 4) {
        float zz = 0.f;
        #pragma unroll
        for (int p = 0; p < NP; p++) zz += g_z[(p * B + b) * S + sb + tid];
        zin[tid] = 1.f / zz;
    }
    for (int i = tid; i < 4 * D; i += 256) prev[i] = g_slots[b * S * D + sb * D + i];
    __syncthreads();
    const float rn = 1.f / (1.f + (float)N * 1e-8f);
    float gv = gin[tid], bv = bein[tid];
    #pragma unroll
    for (int s = 0; s < 4; s++)
        upd[s * D + tid] = gv * ((ua[s] * zin[s] + 1e-8f * hsum) * rn) + bv;
    __syncthreads();
    // ---- uv = updates @ Wv^T ----
    {
        float acc[4] = {0.f, 0.f, 0.f, 0.f};
        const float4* wv4 = (const float4*)(Wv + (size_t)tid * D);
        for (int i = 0; i < D / 4; i++) {
            float4 wv = wv4[i];
            #pragma unroll
            for (int s = 0; s < 4; s++) {
                const float* p = &upd[s * D + i * 4];
                acc[s] += p[0] * wv.x + p[1] * wv.y + p[2] * wv.z + p[3] * wv.w;
            }
        }
        #pragma unroll
        for (int s = 0; s < 4; s++) uv[s * D + tid] = acc[s];
    }
    __syncthreads();
    // ---- GRU ----
    {
        float gi[3][4], gh[3][4];
        for (int gsel = 0; gsel < 3; gsel++) {
            int r = gsel * D + tid;
            const float4* wi = (const float4*)(Wih + (size_t)r * D);
            const float4* wh = (const float4*)(Whh + (size_t)r * D);
            float ai[4] = {0.f, 0.f, 0.f, 0.f}, ah[4] = {0.f, 0.f, 0.f, 0.f};
            for (int i = 0; i < D / 4; i++) {
                float4 a = wi[i], c = wh[i];
                #pragma unroll
                for (int s = 0; s < 4; s++) {
                    const float* pu = &uv[s * D + i * 4];
                    const float* pp = &prev[s * D + i * 4];
                    ai[s] += pu[0] * a.x + pu[1] * a.y + pu[2] * a.z + pu[3] * a.w;
                    ah[s] += pp[0] * c.x + pp[1] * c.y + pp[2] * c.z + pp[3] * c.w;
                }
            }
            float bi2 = bih[r], bh2 = bhh[r];
            #pragma unroll
            for (int s = 0; s < 4; s++) {
                gi[gsel][s] = ai[s] + bi2;
                gh[gsel][s] = ah[s] + bh2;
            }
        }
        #pragma unroll
        for (int s = 0; s < 4; s++) {
            float r = 1.f / (1.f + expf(-(gi[0][s] + gh[0][s])));
            float zz = 1.f / (1.f + expf(-(gi[1][s] + gh[1][s])));
            float nn = tanhf(gi[2][s] + r * gh[2][s]);
            fin[s * D + tid] = (1.f - zz) * nn + zz * prev[s * D + tid];
        }
    }
    __syncthreads();
    // ---- MLP + residual ----
    if (w < 4) ln_row_warp(fin + w * D, sln + w * D, g_ff, be_ff, lane);
    __syncthreads();
    {
        float acc[4] = {0.f, 0.f, 0.f, 0.f};
        const float4* w1 = (const float4*)(W1 + (size_t)tid * D);
        for (int i = 0; i < D / 4; i++) {
            float4 wv = w1[i];
            #pragma unroll
            for (int s = 0; s < 4; s++) {
                const float* p = &sln[s * D + i * 4];
                acc[s] += p[0] * wv.x + p[1] * wv.y + p[2] * wv.z + p[3] * wv.w;
            }
        }
        float b1v = b1[tid];
        #pragma unroll
        for (int s = 0; s < 4; s++) qb[s * D + tid] = fmaxf(acc[s] + b1v, 0.f);
    }
    __syncthreads();
    {
        float a2[4] = {0.f, 0.f, 0.f, 0.f};
        const float4* w2 = (const float4*)(W2 + (size_t)tid * D);
        for (int i = 0; i < D / 4; i++) {
            float4 wv = w2[i];
            #pragma unroll
            for (int s = 0; s < 4; s++) {
                const float* p = &qb[s * D + i * 4];
                a2[s] += p[0] * wv.x + p[1] * wv.y + p[2] * wv.z + p[3] * wv.w;
            }
        }
        float b2v = b2[tid];
        #pragma unroll
        for (int s = 0; s < 4; s++) {
            float o = fin[s * D + tid] + a2[s] + b2v;
            fin[s * D + tid] = o;
            g_slots[b * S * D + sb * D + s * D + tid] = o;
            if (last) out[b * S * D + sb * D + s * D + tid] = o;
        }
    }
    __syncthreads();
    if (!last)
        qproj_tail(fin, sln, qb, red, b, sb, tid, Wq, Wk, g_sl, be_sl, gin);
}

extern "C" void kernel_launch(void* const* d_in, const int* in_sizes, int n_in,
                              void* d_out, int out_size) {
    const float* x        = (const float*)d_in[0];
    const float* noise    = (const float*)d_in[1];
    const float* slots_mu = (const float*)d_in[2];
    const float* slots_ls = (const float*)d_in[3];
    const float* Wq       = (const float*)d_in[4];
    const float* Wk       = (const float*)d_in[5];
    const float* Wv       = (const float*)d_in[6];
    const float* W_ih     = (const float*)d_in[7];
    const float* W_hh     = (const float*)d_in[8];
    const float* b_ih     = (const float*)d_in[9];
    const float* b_hh     = (const float*)d_in[10];
    const float* W1       = (const float*)d_in[11];
    const float* b1       = (const float*)d_in[12];
    const float* W2       = (const float*)d_in[13];
    const float* b2       = (const float*)d_in[14];
    const float* g_in     = (const float*)d_in[15];
    const float* be_in    = (const float*)d_in[16];
    const float* g_sl     = (const float*)d_in[17];
    const float* be_sl    = (const float*)d_in[18];
    const float* g_ff     = (const float*)d_in[19];
    const float* be_ff    = (const float*)d_in[20];
    float* out = (float*)d_out;

    init_slots_kernel<<<(B * S * D) / 256, 256>>>(noise, slots_mu, slots_ls);
    qproj0_kernel<<<B * 2, 256>>>(Wq, Wk, g_sl, be_sl, g_in);
    for (int it = 0; it < 3; it++) {
        fused_attn_kernel<<<dim3(NP, B), 128>>>(x);
        iter_kernel<<<B * 2, 256>>>(g_in, be_in, Wv, W_ih, W_hh, b_ih, b_hh,
                                    W1, b1, W2, b2, g_ff, be_ff, g_sl, be_sl,
                                    Wq, Wk, out, it == 2 ? 1 : 0);
    }
}